// round 1
// baseline (speedup 1.0000x reference)
#include <cuda_runtime.h>
#include <cuda_bf16.h>

// Problem constants
#define BB 4
#define SS 2048
#define TT (BB*SS)        // 8192 tokens
#define HH 1024
#define EE 8
#define KK 2
#define PP (TT*KK)        // 16384 (token, k) pairs

// GEMM tiling
#define BM 128
#define BN 128
#define BKK 8
#define MAXROWS 17408     // PP + EE*(BM-1) rounded up
#define MT (MAXROWS/BM)   // 136 m-tiles max

// ---------------- device scratch (static; no allocations allowed) ----------
__device__ int   d_idx64;            // 1 if top_k_index is int64
__device__ int   d_cnt[EE];
__device__ int   d_cur[EE];
__device__ int   d_padded_total;
__device__ int   d_rowtok[MAXROWS];
__device__ float d_roww[MAXROWS];
__device__ int   d_rowexp[MAXROWS];
__device__ float d_h1[(size_t)MAXROWS * HH];   // layer-1 activations (71 MB)

// ---------------- routing kernels ------------------------------------------

// Detect index dtype (int64 vs int32) by scanning first 2048 32-bit words:
// int64 values in [0,8) have every odd word == 0. Also zero the histograms.
__global__ void k_detect(const int* __restrict__ idx32) {
    __shared__ int s_bad;
    if (threadIdx.x == 0) s_bad = 0;
    __syncthreads();
    for (int i = threadIdx.x; i < 2048; i += blockDim.x) {
        if ((i & 1) && idx32[i] != 0) atomicOr(&s_bad, 1);
    }
    __syncthreads();
    if (threadIdx.x == 0) d_idx64 = s_bad ? 0 : 1;
    if (threadIdx.x < EE) d_cnt[threadIdx.x] = 0;
}

__device__ __forceinline__ int load_expert(const void* idx, int p) {
    int e;
    if (d_idx64) e = (int)((const long long*)idx)[p];
    else         e = ((const int*)idx)[p];
    return e & (EE - 1);   // defensive clamp (E is a power of 2)
}

__global__ void k_count(const void* __restrict__ idx) {
    int p = blockIdx.x * blockDim.x + threadIdx.x;
    if (p >= PP) return;
    atomicAdd(&d_cnt[load_expert(idx, p)], 1);
}

// Single block: exclusive scan of padded counts, init cursors, fill padding rows.
__global__ void k_scan() {
    __shared__ int s_base[EE], s_cnt[EE];
    if (threadIdx.x == 0) {
        int total = 0;
        for (int e = 0; e < EE; e++) {
            int c = d_cnt[e];
            s_cnt[e]  = c;
            s_base[e] = total;
            d_cur[e]  = total;
            total += ((c + BM - 1) / BM) * BM;
        }
        d_padded_total = total;
    }
    __syncthreads();
    for (int e = 0; e < EE; e++) {
        int start = s_base[e] + s_cnt[e];
        int end   = s_base[e] + ((s_cnt[e] + BM - 1) / BM) * BM;
        for (int i = start + threadIdx.x; i < end; i += blockDim.x) {
            d_rowtok[i] = 0;
            d_roww[i]   = 0.0f;
            d_rowexp[i] = e;
        }
    }
}

__global__ void k_scatter(const void* __restrict__ idx,
                          const float* __restrict__ tkw) {
    int p = blockIdx.x * blockDim.x + threadIdx.x;
    if (p >= PP) return;
    int e = load_expert(idx, p);
    int pos = atomicAdd(&d_cur[e], 1);
    d_rowtok[pos] = p / KK;       // token id
    d_roww[pos]   = tkw[p];
    d_rowexp[pos] = e;
}

__global__ void k_zero(float* __restrict__ out, int n) {
    int i = blockIdx.x * blockDim.x + threadIdx.x;
    int stride = gridDim.x * blockDim.x;
    for (; i < n; i += stride) out[i] = 0.0f;
}

// ---------------- batched expert GEMM ---------------------------------------
// LAYER 1: d_h1[row,:] = relu( X[tok[row],:] @ w1[e] + b1[e] )
// LAYER 2: out[tok[row],:] += roww[row] * ( d_h1[row,:] @ w2[e] + b2[e] )
template <int LAYER>
__global__ __launch_bounds__(256, 2)
void k_gemm(const float* __restrict__ X,
            const float* __restrict__ W,
            const float* __restrict__ Bias,
            float* __restrict__ Out) {
    int m0 = blockIdx.x * BM;
    if (m0 >= d_padded_total) return;
    int e  = d_rowexp[m0];
    int n0 = blockIdx.y * BN;

    const float* We = W + (size_t)e * HH * HH;

    __shared__ float As[BKK][BM + 4];   // +4 pad: conflict-free transposed stores
    __shared__ float Bs[BKK][BN];

    int tid  = threadIdx.x;
    // A loader: one float4 per thread  (128 rows x 8 k = 256 float4)
    int arow = tid >> 1;
    int ak0  = (tid & 1) * 4;
    const float* Arow;
    if (LAYER == 1) Arow = X + (size_t)d_rowtok[m0 + arow] * HH;
    else            Arow = d_h1 + (size_t)(m0 + arow) * HH;
    // B loader: one float4 per thread (8 k x 128 n = 256 float4)
    int bk  = tid >> 5;
    int bn0 = (tid & 31) * 4;
    const float* Bptr = We + (size_t)bk * HH + n0 + bn0;

    int tm = (tid >> 4) * 8;
    int tn = (tid & 15) * 8;

    float acc[8][8];
#pragma unroll
    for (int i = 0; i < 8; i++)
#pragma unroll
        for (int j = 0; j < 8; j++) acc[i][j] = 0.0f;

    for (int k0 = 0; k0 < HH; k0 += BKK) {
        float4 av = *(const float4*)(Arow + k0 + ak0);
        As[ak0 + 0][arow] = av.x;
        As[ak0 + 1][arow] = av.y;
        As[ak0 + 2][arow] = av.z;
        As[ak0 + 3][arow] = av.w;
        float4 bv = *(const float4*)(Bptr + (size_t)k0 * HH);
        *(float4*)&Bs[bk][bn0] = bv;
        __syncthreads();
#pragma unroll
        for (int kk = 0; kk < BKK; kk++) {
            float a[8], b[8];
            *(float4*)&a[0] = *(const float4*)&As[kk][tm];
            *(float4*)&a[4] = *(const float4*)&As[kk][tm + 4];
            *(float4*)&b[0] = *(const float4*)&Bs[kk][tn];
            *(float4*)&b[4] = *(const float4*)&Bs[kk][tn + 4];
#pragma unroll
            for (int i = 0; i < 8; i++)
#pragma unroll
                for (int j = 0; j < 8; j++)
                    acc[i][j] += a[i] * b[j];
        }
        __syncthreads();
    }

    const float* be = Bias + e * HH + n0 + tn;
    if (LAYER == 1) {
#pragma unroll
        for (int i = 0; i < 8; i++) {
            size_t r = (size_t)(m0 + tm + i);
            float* o = d_h1 + r * HH + n0 + tn;
#pragma unroll
            for (int j = 0; j < 8; j++) {
                float v = acc[i][j] + be[j];
                o[j] = v > 0.0f ? v : 0.0f;
            }
        }
    } else {
#pragma unroll
        for (int i = 0; i < 8; i++) {
            int r     = m0 + tm + i;
            float w   = d_roww[r];
            int tok   = d_rowtok[r];
            float* o  = Out + (size_t)tok * HH + n0 + tn;
#pragma unroll
            for (int j = 0; j < 8; j++) {
                atomicAdd(&o[j], (acc[i][j] + be[j]) * w);
            }
        }
    }
}

// ---------------- launch ----------------------------------------------------
extern "C" void kernel_launch(void* const* d_in, const int* in_sizes, int n_in,
                              void* d_out, int out_size) {
    const float* hs  = (const float*)d_in[0];
    const void*  idx = d_in[1];
    const float* tkw = (const float*)d_in[2];
    const float* w1  = (const float*)d_in[3];
    const float* b1  = (const float*)d_in[4];
    const float* w2  = (const float*)d_in[5];
    const float* b2  = (const float*)d_in[6];
    float* out = (float*)d_out;

    k_detect<<<1, 256>>>((const int*)idx);
    k_count<<<(PP + 255) / 256, 256>>>(idx);
    k_scan<<<1, 256>>>();
    k_scatter<<<(PP + 255) / 256, 256>>>(idx, tkw);
    k_zero<<<592, 256>>>(out, TT * HH);

    dim3 grid(MT, HH / BN);
    k_gemm<1><<<grid, 256>>>(hs, w1, b1, nullptr);
    k_gemm<2><<<grid, 256>>>(nullptr, w2, b2, out);
}

// round 15
// speedup vs baseline: 3.0291x; 3.0291x over previous
#include <cuda_runtime.h>
#include <cuda_bf16.h>
#include <cstdint>

// ---------------- problem constants ----------------
#define BB 4
#define SS 2048
#define TT (BB*SS)        // 8192 tokens
#define HH 1024
#define EE 8
#define KK 2
#define PP (TT*KK)        // 16384 (token,k) pairs

#define BM 128
#define BN 128
#define BK 16
#define NITER (HH/BK)     // 64 mainloop iterations
#define MAXROWS 17408
#define MT (MAXROWS/BM)   // 136 m-tiles max
#define NT (HH/BN)        // 8 n-tiles
#define SA 20             // smem row stride in floats (16 + 4 pad; 80B, 16B-aligned)

// ---------------- device scratch ----------------
__device__ int   d_idx64;
__device__ int   d_cnt[EE];
__device__ int   d_cur[EE];
__device__ int   d_padded_total;
__device__ int   d_rowtok[MAXROWS];
__device__ float d_roww[MAXROWS];
__device__ int   d_rowexp[MAXROWS];
__device__ float d_h1[(size_t)MAXROWS * HH];          // 71 MB
__device__ float d_wt1[(size_t)EE * HH * HH];         // 32 MB  (w1^T, tf32-rounded)
__device__ float d_wt2[(size_t)EE * HH * HH];         // 32 MB

// ---------------- helpers ----------------
__device__ __forceinline__ float tf32rn(float x) {
    float r;
    asm("cvt.rn.tf32.f32 %0, %1;" : "=f"(r) : "f"(x));
    return r;
}
__device__ __forceinline__ float4 tf32rn4(float4 v) {
    v.x = tf32rn(v.x); v.y = tf32rn(v.y); v.z = tf32rn(v.z); v.w = tf32rn(v.w);
    return v;
}
// m16n8k8 tf32 warp MMA: D = A(16x8,row) * B(8x8,col) + D, fp32 accum
__device__ __forceinline__ void mma_tf32(float* c, uint32_t a0, uint32_t a1,
                                         uint32_t a2, uint32_t a3,
                                         uint32_t b0, uint32_t b1) {
    asm volatile(
        "mma.sync.aligned.m16n8k8.row.col.f32.tf32.tf32.f32 "
        "{%0,%1,%2,%3}, {%4,%5,%6,%7}, {%8,%9}, {%0,%1,%2,%3};"
        : "+f"(c[0]), "+f"(c[1]), "+f"(c[2]), "+f"(c[3])
        : "r"(a0), "r"(a1), "r"(a2), "r"(a3), "r"(b0), "r"(b1));
}

// ---------------- routing kernels (validated R1) ----------------
__global__ void k_detect(const int* __restrict__ idx32) {
    __shared__ int s_bad;
    if (threadIdx.x == 0) s_bad = 0;
    __syncthreads();
    for (int i = threadIdx.x; i < 2048; i += blockDim.x)
        if ((i & 1) && idx32[i] != 0) atomicOr(&s_bad, 1);
    __syncthreads();
    if (threadIdx.x == 0) d_idx64 = s_bad ? 0 : 1;
    if (threadIdx.x < EE) d_cnt[threadIdx.x] = 0;
}
__device__ __forceinline__ int load_expert(const void* idx, int p) {
    int e;
    if (d_idx64) e = (int)((const long long*)idx)[p];
    else         e = ((const int*)idx)[p];
    return e & (EE - 1);
}
__global__ void k_count(const void* __restrict__ idx) {
    int p = blockIdx.x * blockDim.x + threadIdx.x;
    if (p >= PP) return;
    atomicAdd(&d_cnt[load_expert(idx, p)], 1);
}
__global__ void k_scan() {
    __shared__ int s_base[EE], s_cnt[EE];
    if (threadIdx.x == 0) {
        int total = 0;
        for (int e = 0; e < EE; e++) {
            int c = d_cnt[e];
            s_cnt[e] = c; s_base[e] = total; d_cur[e] = total;
            total += ((c + BM - 1) / BM) * BM;
        }
        d_padded_total = total;
    }
    __syncthreads();
    for (int e = 0; e < EE; e++) {
        int start = s_base[e] + s_cnt[e];
        int end   = s_base[e] + ((s_cnt[e] + BM - 1) / BM) * BM;
        for (int i = start + threadIdx.x; i < end; i += blockDim.x) {
            d_rowtok[i] = 0; d_roww[i] = 0.0f; d_rowexp[i] = e;
        }
    }
}
__global__ void k_scatter(const void* __restrict__ idx, const float* __restrict__ tkw) {
    int p = blockIdx.x * blockDim.x + threadIdx.x;
    if (p >= PP) return;
    int e = load_expert(idx, p);
    int pos = atomicAdd(&d_cur[e], 1);
    d_rowtok[pos] = p / KK;
    d_roww[pos]   = tkw[p];
    d_rowexp[pos] = e;
}
__global__ void k_zero(float* __restrict__ out, int n) {
    int i = blockIdx.x * blockDim.x + threadIdx.x;
    int stride = gridDim.x * blockDim.x;
    for (; i < n; i += stride) out[i] = 0.0f;
}

// ---------------- weight transpose + tf32 RN round: WT[e][n][k] = rn(W[e][k][n]) ----
__global__ void k_transpose(const float* __restrict__ W, float* __restrict__ WT) {
    __shared__ float t[32][33];
    int e = blockIdx.z;
    const float* w = W  + (size_t)e * HH * HH;
    float*       o = WT + (size_t)e * HH * HH;
    int x  = blockIdx.x * 32 + threadIdx.x;
    int y0 = blockIdx.y * 32;
#pragma unroll
    for (int i = threadIdx.y; i < 32; i += 8)
        t[i][threadIdx.x] = tf32rn(w[(size_t)(y0 + i) * HH + x]);
    __syncthreads();
    int xo = blockIdx.y * 32 + threadIdx.x;
    int nb = blockIdx.x * 32;
#pragma unroll
    for (int i = threadIdx.y; i < 32; i += 8)
        o[(size_t)(nb + i) * HH + xo] = t[threadIdx.x][i];
}

// ---------------- mma.sync tf32 routed GEMM ----------------
// 128x128x16 CTA tile, 256 thr = 8 warps (2 m x 4 n), warp tile 64x32.
// A: routed rows (gathered via row pointers). B: W^T (k-contiguous).
template <int LAYER>
__global__ __launch_bounds__(256, 2)
void k_gemm_mma(const float* __restrict__ X,
                const float* __restrict__ WT,
                const float* __restrict__ Bias,
                float* __restrict__ Out) {
    __shared__ float As[BM * SA];
    __shared__ float Bs[BN * SA];

    int m0 = blockIdx.x * BM;
    if (m0 >= d_padded_total) return;
    int e  = d_rowexp[m0];
    int n0 = blockIdx.y * BN;

    int tid  = threadIdx.x;
    int wid  = tid >> 5, lane = tid & 31;
    int g    = lane >> 2, tig = lane & 3;
    int wm   = wid >> 2;        // 0..1 -> m offset wm*64
    int wn   = wid & 3;         // 0..3 -> n offset wn*32

    // Loader mapping: each thread owns rows r0 = tid>>2 and r1 = 64 + (tid>>2),
    // column chunk c4 = tid&3 (float4 at k-offset c4*4).
    int r0 = tid >> 2, r1 = 64 + r0, c4 = tid & 3;
    const float* arow0;
    const float* arow1;
    if (LAYER == 1) {
        arow0 = X + (size_t)d_rowtok[m0 + r0] * HH;
        arow1 = X + (size_t)d_rowtok[m0 + r1] * HH;
    } else {
        arow0 = d_h1 + (size_t)(m0 + r0) * HH;
        arow1 = d_h1 + (size_t)(m0 + r1) * HH;
    }
    const float* WTe = WT + (size_t)e * HH * HH + (size_t)n0 * HH;
    const float* brow0 = WTe + (size_t)r0 * HH;
    const float* brow1 = WTe + (size_t)r1 * HH;

    float acc[4][4][4];
#pragma unroll
    for (int mi = 0; mi < 4; mi++)
#pragma unroll
        for (int ni = 0; ni < 4; ni++)
#pragma unroll
            for (int q = 0; q < 4; q++) acc[mi][ni][q] = 0.0f;

    // Prefetch first chunk (A rounded to tf32-RN; B pre-rounded in transpose).
    float4 pa0 = tf32rn4(*(const float4*)(arow0 + c4 * 4));
    float4 pa1 = tf32rn4(*(const float4*)(arow1 + c4 * 4));
    float4 pb0 = *(const float4*)(brow0 + c4 * 4);
    float4 pb1 = *(const float4*)(brow1 + c4 * 4);

    for (int c = 0; c < NITER; c++) {
        __syncthreads();   // previous iter's smem reads complete
        *(float4*)(As + r0 * SA + c4 * 4) = pa0;
        *(float4*)(As + r1 * SA + c4 * 4) = pa1;
        *(float4*)(Bs + r0 * SA + c4 * 4) = pb0;
        *(float4*)(Bs + r1 * SA + c4 * 4) = pb1;
        __syncthreads();
        if (c + 1 < NITER) {
            int k0 = (c + 1) * BK + c4 * 4;
            pa0 = tf32rn4(*(const float4*)(arow0 + k0));
            pa1 = tf32rn4(*(const float4*)(arow1 + k0));
            pb0 = *(const float4*)(brow0 + k0);
            pb1 = *(const float4*)(brow1 + k0);
        }
#pragma unroll
        for (int ks = 0; ks < BK; ks += 8) {
            uint32_t a[4][4], b[4][2];
#pragma unroll
            for (int mi = 0; mi < 4; mi++) {
                int row = wm * 64 + mi * 16;
                a[mi][0] = __float_as_uint(As[(row + g)     * SA + ks + tig]);
                a[mi][1] = __float_as_uint(As[(row + g + 8) * SA + ks + tig]);
                a[mi][2] = __float_as_uint(As[(row + g)     * SA + ks + tig + 4]);
                a[mi][3] = __float_as_uint(As[(row + g + 8) * SA + ks + tig + 4]);
            }
#pragma unroll
            for (int ni = 0; ni < 4; ni++) {
                int nb = wn * 32 + ni * 8;
                b[ni][0] = __float_as_uint(Bs[(nb + g) * SA + ks + tig]);
                b[ni][1] = __float_as_uint(Bs[(nb + g) * SA + ks + tig + 4]);
            }
#pragma unroll
            for (int mi = 0; mi < 4; mi++)
#pragma unroll
                for (int ni = 0; ni < 4; ni++)
                    mma_tf32(acc[mi][ni], a[mi][0], a[mi][1], a[mi][2], a[mi][3],
                             b[ni][0], b[ni][1]);
        }
    }

    // Bias (registers; cols depend only on ni/tig/wn).
    float2 bias2[4];
#pragma unroll
    for (int ni = 0; ni < 4; ni++)
        bias2[ni] = *(const float2*)(Bias + e * HH + n0 + wn * 32 + ni * 8 + 2 * tig);

#pragma unroll
    for (int mi = 0; mi < 4; mi++) {
        int rl = m0 + wm * 64 + mi * 16 + g;
        int rh = rl + 8;
        if (LAYER == 1) {
            float* ol = d_h1 + (size_t)rl * HH + n0;
            float* oh = d_h1 + (size_t)rh * HH + n0;
#pragma unroll
            for (int ni = 0; ni < 4; ni++) {
                int col = wn * 32 + ni * 8 + 2 * tig;
                float2 v0, v1;
                v0.x = fmaxf(acc[mi][ni][0] + bias2[ni].x, 0.0f);
                v0.y = fmaxf(acc[mi][ni][1] + bias2[ni].y, 0.0f);
                v1.x = fmaxf(acc[mi][ni][2] + bias2[ni].x, 0.0f);
                v1.y = fmaxf(acc[mi][ni][3] + bias2[ni].y, 0.0f);
                *(float2*)(ol + col) = v0;
                *(float2*)(oh + col) = v1;
            }
        } else {
            float wl = d_roww[rl], wh = d_roww[rh];
            int   tl = d_rowtok[rl], th = d_rowtok[rh];
            float* ol = Out + (size_t)tl * HH + n0;
            float* oh = Out + (size_t)th * HH + n0;
#pragma unroll
            for (int ni = 0; ni < 4; ni++) {
                int col = wn * 32 + ni * 8 + 2 * tig;
                float s0 = (acc[mi][ni][0] + bias2[ni].x) * wl;
                float s1 = (acc[mi][ni][1] + bias2[ni].y) * wl;
                float s2 = (acc[mi][ni][2] + bias2[ni].x) * wh;
                float s3 = (acc[mi][ni][3] + bias2[ni].y) * wh;
                asm volatile("red.global.add.f32 [%0], %1;" :: "l"(ol + col),     "f"(s0) : "memory");
                asm volatile("red.global.add.f32 [%0], %1;" :: "l"(ol + col + 1), "f"(s1) : "memory");
                asm volatile("red.global.add.f32 [%0], %1;" :: "l"(oh + col),     "f"(s2) : "memory");
                asm volatile("red.global.add.f32 [%0], %1;" :: "l"(oh + col + 1), "f"(s3) : "memory");
            }
        }
    }
}

// ---------------- launch ----------------
extern "C" void kernel_launch(void* const* d_in, const int* in_sizes, int n_in,
                              void* d_out, int out_size) {
    const float* hs  = (const float*)d_in[0];
    const void*  idx = d_in[1];
    const float* tkw = (const float*)d_in[2];
    const float* w1  = (const float*)d_in[3];
    const float* b1  = (const float*)d_in[4];
    const float* w2  = (const float*)d_in[5];
    const float* b2  = (const float*)d_in[6];
    float* out = (float*)d_out;

    float* wt1; cudaGetSymbolAddress((void**)&wt1, d_wt1);
    float* wt2; cudaGetSymbolAddress((void**)&wt2, d_wt2);

    k_detect<<<1, 256>>>((const int*)idx);
    k_count<<<(PP + 255) / 256, 256>>>(idx);
    k_scan<<<1, 256>>>();
    k_scatter<<<(PP + 255) / 256, 256>>>(idx, tkw);
    k_zero<<<592, 256>>>(out, TT * HH);

    dim3 tgrid(HH / 32, HH / 32, EE);
    k_transpose<<<tgrid, dim3(32, 8)>>>(w1, wt1);
    k_transpose<<<tgrid, dim3(32, 8)>>>(w2, wt2);

    dim3 grid(MT, NT);
    k_gemm_mma<1><<<grid, 256>>>(hs, wt1, b1, nullptr);
    k_gemm_mma<2><<<grid, 256>>>(nullptr, wt2, b2, out);
}

// round 16
// speedup vs baseline: 3.3059x; 1.0914x over previous
#include <cuda_runtime.h>
#include <cuda_bf16.h>
#include <cstdint>

// ---------------- problem constants ----------------
#define BB 4
#define SS 2048
#define TT (BB*SS)        // 8192 tokens
#define HH 1024
#define EE 8
#define KK 2
#define PP (TT*KK)        // 16384 (token,k) pairs

#define BM 128
#define BN 128
#define BK 16
#define NITER (HH/BK)     // 64 mainloop iterations
#define MAXROWS 17408
#define MT (MAXROWS/BM)   // 136 m-tiles max
#define NT (HH/BN)        // 8 n-tiles
#define SA 20             // smem row stride in floats (16 + 4 pad)
#define STAGE_F (BM * SA) // floats per stage (A and B identical)

// ---------------- device scratch ----------------
__device__ int   d_idx64;
__device__ int   d_cnt[EE];
__device__ int   d_cur[EE];
__device__ int   d_padded_total;
__device__ int   d_rowtok[MAXROWS];
__device__ float d_roww[MAXROWS];
__device__ int   d_rowexp[MAXROWS];
__device__ float d_h1[(size_t)MAXROWS * HH];          // 71 MB (tf32-rounded)
__device__ float d_xr[(size_t)TT * HH];               // 33 MB (X tf32-rounded)
__device__ float d_wt1[(size_t)EE * HH * HH];         // 32 MB (w1^T tf32-rounded)
__device__ float d_wt2[(size_t)EE * HH * HH];         // 32 MB

// ---------------- helpers ----------------
__device__ __forceinline__ float tf32rn(float x) {
    float r;
    asm("cvt.rn.tf32.f32 %0, %1;" : "=f"(r) : "f"(x));
    return r;
}
__device__ __forceinline__ uint32_t smem_u32(const void* p) {
    uint32_t a;
    asm("{ .reg .u64 t; cvta.to.shared.u64 t, %1; cvt.u32.u64 %0, t; }" : "=r"(a) : "l"(p));
    return a;
}
__device__ __forceinline__ void cp16(uint32_t s, const void* g) {
    asm volatile("cp.async.cg.shared.global [%0], [%1], 16;" :: "r"(s), "l"(g));
}
#define CP_COMMIT() asm volatile("cp.async.commit_group;" ::: "memory")
#define CP_WAIT(n)  asm volatile("cp.async.wait_group %0;" :: "n"(n) : "memory")

// m16n8k8 tf32 warp MMA
__device__ __forceinline__ void mma_tf32(float* c, uint32_t a0, uint32_t a1,
                                         uint32_t a2, uint32_t a3,
                                         uint32_t b0, uint32_t b1) {
    asm volatile(
        "mma.sync.aligned.m16n8k8.row.col.f32.tf32.tf32.f32 "
        "{%0,%1,%2,%3}, {%4,%5,%6,%7}, {%8,%9}, {%0,%1,%2,%3};"
        : "+f"(c[0]), "+f"(c[1]), "+f"(c[2]), "+f"(c[3])
        : "r"(a0), "r"(a1), "r"(a2), "r"(a3), "r"(b0), "r"(b1));
}

// ---------------- routing kernels (validated R1) ----------------
__global__ void k_detect(const int* __restrict__ idx32) {
    __shared__ int s_bad;
    if (threadIdx.x == 0) s_bad = 0;
    __syncthreads();
    for (int i = threadIdx.x; i < 2048; i += blockDim.x)
        if ((i & 1) && idx32[i] != 0) atomicOr(&s_bad, 1);
    __syncthreads();
    if (threadIdx.x == 0) d_idx64 = s_bad ? 0 : 1;
    if (threadIdx.x < EE) d_cnt[threadIdx.x] = 0;
}
__device__ __forceinline__ int load_expert(const void* idx, int p) {
    int e;
    if (d_idx64) e = (int)((const long long*)idx)[p];
    else         e = ((const int*)idx)[p];
    return e & (EE - 1);
}
__global__ void k_count(const void* __restrict__ idx) {
    int p = blockIdx.x * blockDim.x + threadIdx.x;
    if (p >= PP) return;
    atomicAdd(&d_cnt[load_expert(idx, p)], 1);
}
__global__ void k_scan() {
    __shared__ int s_base[EE], s_cnt[EE];
    if (threadIdx.x == 0) {
        int total = 0;
        for (int e = 0; e < EE; e++) {
            int c = d_cnt[e];
            s_cnt[e] = c; s_base[e] = total; d_cur[e] = total;
            total += ((c + BM - 1) / BM) * BM;
        }
        d_padded_total = total;
    }
    __syncthreads();
    for (int e = 0; e < EE; e++) {
        int start = s_base[e] + s_cnt[e];
        int end   = s_base[e] + ((s_cnt[e] + BM - 1) / BM) * BM;
        for (int i = start + threadIdx.x; i < end; i += blockDim.x) {
            d_rowtok[i] = 0; d_roww[i] = 0.0f; d_rowexp[i] = e;
        }
    }
}
__global__ void k_scatter(const void* __restrict__ idx, const float* __restrict__ tkw) {
    int p = blockIdx.x * blockDim.x + threadIdx.x;
    if (p >= PP) return;
    int e = load_expert(idx, p);
    int pos = atomicAdd(&d_cur[e], 1);
    d_rowtok[pos] = p / KK;
    d_roww[pos]   = tkw[p];
    d_rowexp[pos] = e;
}
__global__ void k_zero(float* __restrict__ out, int n) {
    int i = blockIdx.x * blockDim.x + threadIdx.x;
    int stride = gridDim.x * blockDim.x;
    for (; i < n; i += stride) out[i] = 0.0f;
}
// Round X to tf32 (float4 grid-stride) so cp.async can copy raw bytes.
__global__ void k_round(const float* __restrict__ in, float* __restrict__ out, int n4) {
    int i = blockIdx.x * blockDim.x + threadIdx.x;
    int stride = gridDim.x * blockDim.x;
    for (; i < n4; i += stride) {
        float4 v = ((const float4*)in)[i];
        v.x = tf32rn(v.x); v.y = tf32rn(v.y); v.z = tf32rn(v.z); v.w = tf32rn(v.w);
        ((float4*)out)[i] = v;
    }
}

// ---------------- weight transpose + tf32 RN round ----------------
__global__ void k_transpose(const float* __restrict__ W, float* __restrict__ WT) {
    __shared__ float t[32][33];
    int e = blockIdx.z;
    const float* w = W  + (size_t)e * HH * HH;
    float*       o = WT + (size_t)e * HH * HH;
    int x  = blockIdx.x * 32 + threadIdx.x;
    int y0 = blockIdx.y * 32;
#pragma unroll
    for (int i = threadIdx.y; i < 32; i += 8)
        t[i][threadIdx.x] = tf32rn(w[(size_t)(y0 + i) * HH + x]);
    __syncthreads();
    int xo = blockIdx.y * 32 + threadIdx.x;
    int nb = blockIdx.x * 32;
#pragma unroll
    for (int i = threadIdx.y; i < 32; i += 8)
        o[(size_t)(nb + i) * HH + xo] = t[threadIdx.x][i];
}

// ---------------- mma.sync tf32 routed GEMM, cp.async 2-stage ----------------
template <int LAYER>
__global__ __launch_bounds__(256, 2)
void k_gemm_mma(const float* __restrict__ X,
                const float* __restrict__ WT,
                const float* __restrict__ Bias,
                float* __restrict__ Out) {
    __shared__ float As[2 * STAGE_F];
    __shared__ float Bs[2 * STAGE_F];

    int m0 = blockIdx.x * BM;
    if (m0 >= d_padded_total) return;
    int e  = d_rowexp[m0];
    int n0 = blockIdx.y * BN;

    int tid  = threadIdx.x;
    int wid  = tid >> 5, lane = tid & 31;
    int g    = lane >> 2, tig = lane & 3;
    int wm   = wid >> 2;
    int wn   = wid & 3;

    int r0 = tid >> 2, r1 = 64 + r0, c4 = tid & 3;
    const float* arow0;
    const float* arow1;
    if (LAYER == 1) {
        arow0 = X + (size_t)d_rowtok[m0 + r0] * HH;
        arow1 = X + (size_t)d_rowtok[m0 + r1] * HH;
    } else {
        arow0 = d_h1 + (size_t)(m0 + r0) * HH;
        arow1 = d_h1 + (size_t)(m0 + r1) * HH;
    }
    const float* WTe = WT + (size_t)e * HH * HH + (size_t)n0 * HH;
    const float* brow0 = WTe + (size_t)r0 * HH;
    const float* brow1 = WTe + (size_t)r1 * HH;

    // cp.async destinations (per-thread, fixed offsets)
    const uint32_t stage_b = STAGE_F * 4;
    uint32_t sa0 = smem_u32(As) + (uint32_t)(r0 * SA + c4 * 4) * 4;
    uint32_t sa1 = smem_u32(As) + (uint32_t)(r1 * SA + c4 * 4) * 4;
    uint32_t sb0 = smem_u32(Bs) + (uint32_t)(r0 * SA + c4 * 4) * 4;
    uint32_t sb1 = smem_u32(Bs) + (uint32_t)(r1 * SA + c4 * 4) * 4;
    int koff = c4 * 4;

    float acc[4][4][4];
#pragma unroll
    for (int mi = 0; mi < 4; mi++)
#pragma unroll
        for (int ni = 0; ni < 4; ni++)
#pragma unroll
            for (int q = 0; q < 4; q++) acc[mi][ni][q] = 0.0f;

    // Prologue: stage 0
    cp16(sa0, arow0 + koff); cp16(sa1, arow1 + koff);
    cp16(sb0, brow0 + koff); cp16(sb1, brow1 + koff);
    CP_COMMIT();

    for (int c = 0; c < NITER; c++) {
        if (c + 1 < NITER) {
            uint32_t st = (uint32_t)((c + 1) & 1) * stage_b;
            int k0 = (c + 1) * BK + koff;
            cp16(sa0 + st, arow0 + k0); cp16(sa1 + st, arow1 + k0);
            cp16(sb0 + st, brow0 + k0); cp16(sb1 + st, brow1 + k0);
            CP_COMMIT();
            CP_WAIT(1);
        } else {
            CP_WAIT(0);
        }
        __syncthreads();
        const float* A = As + (c & 1) * STAGE_F;
        const float* B = Bs + (c & 1) * STAGE_F;
#pragma unroll
        for (int ks = 0; ks < BK; ks += 8) {
            uint32_t a[4][4], b[4][2];
#pragma unroll
            for (int mi = 0; mi < 4; mi++) {
                int row = wm * 64 + mi * 16;
                a[mi][0] = __float_as_uint(A[(row + g)     * SA + ks + tig]);
                a[mi][1] = __float_as_uint(A[(row + g + 8) * SA + ks + tig]);
                a[mi][2] = __float_as_uint(A[(row + g)     * SA + ks + tig + 4]);
                a[mi][3] = __float_as_uint(A[(row + g + 8) * SA + ks + tig + 4]);
            }
#pragma unroll
            for (int ni = 0; ni < 4; ni++) {
                int nb = wn * 32 + ni * 8;
                b[ni][0] = __float_as_uint(B[(nb + g) * SA + ks + tig]);
                b[ni][1] = __float_as_uint(B[(nb + g) * SA + ks + tig + 4]);
            }
#pragma unroll
            for (int mi = 0; mi < 4; mi++)
#pragma unroll
                for (int ni = 0; ni < 4; ni++)
                    mma_tf32(acc[mi][ni], a[mi][0], a[mi][1], a[mi][2], a[mi][3],
                             b[ni][0], b[ni][1]);
        }
        __syncthreads();
    }

    float2 bias2[4];
#pragma unroll
    for (int ni = 0; ni < 4; ni++)
        bias2[ni] = *(const float2*)(Bias + e * HH + n0 + wn * 32 + ni * 8 + 2 * tig);

#pragma unroll
    for (int mi = 0; mi < 4; mi++) {
        int rl = m0 + wm * 64 + mi * 16 + g;
        int rh = rl + 8;
        if (LAYER == 1) {
            float* ol = d_h1 + (size_t)rl * HH + n0;
            float* oh = d_h1 + (size_t)rh * HH + n0;
#pragma unroll
            for (int ni = 0; ni < 4; ni++) {
                int col = wn * 32 + ni * 8 + 2 * tig;
                float2 v0, v1;
                v0.x = tf32rn(fmaxf(acc[mi][ni][0] + bias2[ni].x, 0.0f));
                v0.y = tf32rn(fmaxf(acc[mi][ni][1] + bias2[ni].y, 0.0f));
                v1.x = tf32rn(fmaxf(acc[mi][ni][2] + bias2[ni].x, 0.0f));
                v1.y = tf32rn(fmaxf(acc[mi][ni][3] + bias2[ni].y, 0.0f));
                *(float2*)(ol + col) = v0;
                *(float2*)(oh + col) = v1;
            }
        } else {
            float wl = d_roww[rl], wh = d_roww[rh];
            int   tl = d_rowtok[rl], th = d_rowtok[rh];
            float* ol = Out + (size_t)tl * HH + n0;
            float* oh = Out + (size_t)th * HH + n0;
#pragma unroll
            for (int ni = 0; ni < 4; ni++) {
                int col = wn * 32 + ni * 8 + 2 * tig;
                float s0 = (acc[mi][ni][0] + bias2[ni].x) * wl;
                float s1 = (acc[mi][ni][1] + bias2[ni].y) * wl;
                float s2 = (acc[mi][ni][2] + bias2[ni].x) * wh;
                float s3 = (acc[mi][ni][3] + bias2[ni].y) * wh;
                asm volatile("red.global.add.f32 [%0], %1;" :: "l"(ol + col),     "f"(s0) : "memory");
                asm volatile("red.global.add.f32 [%0], %1;" :: "l"(ol + col + 1), "f"(s1) : "memory");
                asm volatile("red.global.add.f32 [%0], %1;" :: "l"(oh + col),     "f"(s2) : "memory");
                asm volatile("red.global.add.f32 [%0], %1;" :: "l"(oh + col + 1), "f"(s3) : "memory");
            }
        }
    }
}

// ---------------- launch ----------------
extern "C" void kernel_launch(void* const* d_in, const int* in_sizes, int n_in,
                              void* d_out, int out_size) {
    const float* hs  = (const float*)d_in[0];
    const void*  idx = d_in[1];
    const float* tkw = (const float*)d_in[2];
    const float* w1  = (const float*)d_in[3];
    const float* b1  = (const float*)d_in[4];
    const float* w2  = (const float*)d_in[5];
    const float* b2  = (const float*)d_in[6];
    float* out = (float*)d_out;

    float* wt1; cudaGetSymbolAddress((void**)&wt1, d_wt1);
    float* wt2; cudaGetSymbolAddress((void**)&wt2, d_wt2);
    float* xr;  cudaGetSymbolAddress((void**)&xr,  d_xr);

    k_detect<<<1, 256>>>((const int*)idx);
    k_count<<<(PP + 255) / 256, 256>>>(idx);
    k_scan<<<1, 256>>>();
    k_scatter<<<(PP + 255) / 256, 256>>>(idx, tkw);
    k_zero<<<592, 256>>>(out, TT * HH);
    k_round<<<1184, 256>>>(hs, xr, TT * HH / 4);

    dim3 tgrid(HH / 32, HH / 32, EE);
    k_transpose<<<tgrid, dim3(32, 8)>>>(w1, wt1);
    k_transpose<<<tgrid, dim3(32, 8)>>>(w2, wt2);

    dim3 grid(MT, NT);
    k_gemm_mma<1><<<grid, 256>>>(xr, wt1, b1, nullptr);
    k_gemm_mma<2><<<grid, 256>>>(nullptr, wt2, b2, out);
}